// round 6
// baseline (speedup 1.0000x reference)
#include <cuda_runtime.h>
#include <cuda_fp16.h>
#include <cstdint>
#include <math.h>

// Problem dims (fixed by the dataset)
#define NTOK   8192            // B*S = 4*2048
#define HD     1024
#define FD     4096
#define NE     8
#define NPAIR  (NTOK * 2)      // top-2

// ---------------- scratch (__device__ globals: allocation-rule safe) --------
__device__ int    g_count[NE];
__device__ int    g_list[NE][NTOK];           // pair ids (t*2+k) per expert
__device__ float  g_pairw[NPAIR];             // gate prob per pair slot
__device__ __half g_w1h[(size_t)NE * HD * FD];   // 67 MB  [e][H][F]
__device__ __half g_w2h[(size_t)NE * FD * HD];   // 67 MB  [e][F][H]
__device__ __half g_xh[(size_t)NTOK * HD];       // 16 MB
__device__ __half g_hh[(size_t)NPAIR * FD];      // 134 MB fp16 intermediate

// ---------------- fp32 -> fp16 convert --------------------------------------
__global__ void cvt_f2h(const float4* __restrict__ s, int which, int n4) {
    int i = blockIdx.x * blockDim.x + threadIdx.x;
    if (i >= n4) return;
    __half2* dst = (which == 0) ? (__half2*)g_w1h
                 : (which == 1) ? (__half2*)g_w2h
                                : (__half2*)g_xh;
    float4 v = s[i];
    uint2 o;
    *reinterpret_cast<__half2*>(&o.x) = __floats2half2_rn(v.x, v.y);
    *reinterpret_cast<__half2*>(&o.y) = __floats2half2_rn(v.z, v.w);
    reinterpret_cast<uint2*>(dst)[i] = o;
}

// ---------------- reset: zero output + counters (every replay!) -------------
__global__ void reset_kernel(float4* out4, int n4) {
    int i = blockIdx.x * blockDim.x + threadIdx.x;
    if (i < n4) out4[i] = make_float4(0.f, 0.f, 0.f, 0.f);
    if (i < NE) g_count[i] = 0;
}

// ---------------- gating: logits, softmax, top-2, build gather lists --------
__global__ void gate_kernel(const float* __restrict__ x,
                            const float* __restrict__ gw) {
    const int t = blockIdx.x;
    const int warp = threadIdx.x >> 5, lane = threadIdx.x & 31;
    __shared__ float logits[NE];
    const float* xr = x + (size_t)t * HD;
    const float* wr = gw + warp * HD;       // 8 warps = 8 experts
    float s = 0.f;
#pragma unroll 8
    for (int h = lane; h < HD; h += 32) s = fmaf(xr[h], wr[h], s);
#pragma unroll
    for (int o = 16; o > 0; o >>= 1) s += __shfl_xor_sync(0xffffffffu, s, o);
    if (lane == 0) logits[warp] = s;
    __syncthreads();
    if (threadIdx.x == 0) {
        float mx = logits[0];
        for (int e = 1; e < NE; e++) mx = fmaxf(mx, logits[e]);
        float pe[NE]; float den = 0.f;
        for (int e = 0; e < NE; e++) { pe[e] = expf(logits[e] - mx); den += pe[e]; }
        int i1 = 0;
        for (int e = 1; e < NE; e++) if (pe[e] > pe[i1]) i1 = e;  // lowest idx on tie
        int i2 = (i1 == 0) ? 1 : 0;
        for (int e = 0; e < NE; e++) if (e != i1 && pe[e] > pe[i2]) i2 = e;
        float inv = 1.f / den;
        int p0 = t * 2, p1 = t * 2 + 1;
        g_pairw[p0] = pe[i1] * inv;
        g_pairw[p1] = pe[i2] * inv;
        int k0 = atomicAdd(&g_count[i1], 1); g_list[i1][k0] = p0;
        int k1 = atomicAdd(&g_count[i2], 1); g_list[i2][k1] = p1;
    }
}

// ---------------- mma / ldmatrix helpers ------------------------------------
__device__ __forceinline__ void mma_f16(float c[4], const uint32_t a[4],
                                        uint32_t b0, uint32_t b1) {
    asm volatile(
        "mma.sync.aligned.m16n8k16.row.col.f32.f16.f16.f32 "
        "{%0,%1,%2,%3},{%4,%5,%6,%7},{%8,%9},{%0,%1,%2,%3};\n"
        : "+f"(c[0]), "+f"(c[1]), "+f"(c[2]), "+f"(c[3])
        : "r"(a[0]), "r"(a[1]), "r"(a[2]), "r"(a[3]), "r"(b0), "r"(b1));
}
__device__ __forceinline__ void ldsm_x4(uint32_t r[4], uint32_t a) {
    asm volatile("ldmatrix.sync.aligned.m8n8.x4.shared.b16 {%0,%1,%2,%3},[%4];\n"
                 : "=r"(r[0]), "=r"(r[1]), "=r"(r[2]), "=r"(r[3]) : "r"(a));
}
__device__ __forceinline__ void ldsm_x4_t(uint32_t r[4], uint32_t a) {
    asm volatile("ldmatrix.sync.aligned.m8n8.x4.trans.shared.b16 {%0,%1,%2,%3},[%4];\n"
                 : "=r"(r[0]), "=r"(r[1]), "=r"(r[2]), "=r"(r[3]) : "r"(a));
}
__device__ __forceinline__ void cp16(uint32_t dst, const void* src) {
    asm volatile("cp.async.cg.shared.global [%0], [%1], 16;\n" :: "r"(dst), "l"(src));
}

// ---------------- grouped gather-GEMM (fp16 in, fp32 acc) -------------------
// CTA tile 128x256, 8 warps of 64x64, BK=32, 3-stage cp.async pipeline.
// MODE 0: g_hh[p] = silu(xh[t] @ w1h[e] + b1[e])        M=cnt K=HD  N=FD
// MODE 1: out[t] += pairw[p]*(g_hh[p] @ w2h[e] + b2[e]) M=cnt K=FD  N=HD
#define BM 128
#define BN 256
#define BK 32
#define STAGES 3
#define AS 40                  // A row stride in halves (80B, 16B-aligned)
#define BS2 264                // B row stride in halves (528B, 16B-aligned)
#define A_BYTES (BM * AS * 2)          // 10240
#define STAGE_B (A_BYTES + BK * BS2 * 2)  // 10240 + 16896 = 27136

template <int MODE>
__global__ __launch_bounds__(256)
void moe_gemm(const float* __restrict__ b1g, const float* __restrict__ b2g,
              float* __restrict__ out) {
    constexpr int K = (MODE == 0) ? HD : FD;
    constexpr int N = (MODE == 0) ? FD : HD;
    constexpr int KT = K / BK;
    const int e = blockIdx.z;
    const int cnt = g_count[e];
    const int rowBase = blockIdx.y * BM;
    if (rowBase >= cnt) return;                 // idle worst-case block
    const int n0 = blockIdx.x * BN;
    const __half* __restrict__ Bmat =
        (MODE == 0) ? (g_w1h + (size_t)e * HD * FD) : (g_w2h + (size_t)e * FD * HD);
    const float* __restrict__ bias = (MODE == 0) ? (b1g + e * FD) : (b2g + e * HD);

    extern __shared__ __align__(128) char dsm[];
    __shared__ int rowP[BM];
    __shared__ const __half* rowSrc[BM];
    __shared__ float bias_s[BN];

    const int tid = threadIdx.x;
    if (tid < BM) {
        int gi = rowBase + tid;
        int pp = (gi < cnt) ? g_list[e][gi] : -1;
        rowP[tid] = pp;
        rowSrc[tid] = (MODE == 0)
            ? ((pp >= 0) ? g_xh + (size_t)(pp >> 1) * HD : g_xh)
            : ((pp >= 0) ? g_hh + (size_t)pp * FD : g_hh);
    }
    bias_s[tid] = bias[n0 + tid];               // BN==256: one element per thread
    __syncthreads();

    const int lane = tid & 31, warp = tid >> 5;
    const int wm = (warp & 1) * 64;            // 2x4 warp grid, 64x64 warp tile
    const int wn = (warp >> 1) * 64;
    const int grp = lane >> 2, quad = lane & 3;
    const uint32_t dsm32 = (uint32_t)__cvta_generic_to_shared(dsm);

    float acc[4][8][4];
#pragma unroll
    for (int a = 0; a < 4; a++)
#pragma unroll
        for (int b = 0; b < 8; b++)
#pragma unroll
            for (int c = 0; c < 4; c++) acc[a][b][c] = 0.f;

    auto fill = [&](int s, int kt) {
        const int k0 = kt * BK;
        const uint32_t aB = dsm32 + s * STAGE_B;
        const uint32_t bB = aB + A_BYTES;
#pragma unroll
        for (int i = 0; i < 2; ++i) {           // A: 128 rows x 4 chunks = 512
            int id = tid + i * 256;
            int r = id >> 2, ch = id & 3;       // FIX: full 32-half rows
            cp16(aB + (r * AS + ch * 8) * 2, rowSrc[r] + k0 + ch * 8);
        }
#pragma unroll
        for (int i = 0; i < 4; ++i) {           // B: 32 rows x 32 chunks = 1024
            int id = tid + i * 256;
            int r = id >> 5, ch = id & 31;
            cp16(bB + (r * BS2 + ch * 8) * 2,
                 Bmat + (size_t)(k0 + r) * N + n0 + ch * 8);
        }
        asm volatile("cp.async.commit_group;\n" ::: "memory");
    };

    fill(0, 0);
    fill(1, 1);
    for (int kt = 0; kt < KT; ++kt) {
        if (kt + 2 < KT) {
            fill((kt + 2) % STAGES, kt + 2);    // stage freed at end of kt-1
            asm volatile("cp.async.wait_group 2;\n" ::: "memory");
        } else if (kt + 1 < KT) {
            asm volatile("cp.async.wait_group 1;\n" ::: "memory");
        } else {
            asm volatile("cp.async.wait_group 0;\n" ::: "memory");
        }
        __syncthreads();
        const int s = kt % STAGES;
        const uint32_t aB = dsm32 + s * STAGE_B;
        const uint32_t bB = aB + A_BYTES;
#pragma unroll
        for (int ks = 0; ks < 2; ++ks) {        // two k16 steps per BK=32
            uint32_t af[4][4];
#pragma unroll
            for (int mi = 0; mi < 4; ++mi) {
                int row = wm + mi * 16 + (lane & 15);
                int col = ks * 16 + (lane >> 4) * 8;
                ldsm_x4(af[mi], aB + (row * AS + col) * 2);
            }
            uint32_t bf[4][4];
#pragma unroll
            for (int np = 0; np < 4; ++np) {
                int m = lane >> 3;
                int kk = ks * 16 + (m & 1) * 8 + (lane & 7);
                int nn = wn + np * 16 + (m >> 1) * 8;
                ldsm_x4_t(bf[np], bB + (kk * BS2 + nn) * 2);
            }
#pragma unroll
            for (int mi = 0; mi < 4; ++mi) {
#pragma unroll
                for (int np = 0; np < 4; ++np) {
                    mma_f16(acc[mi][np * 2 + 0], af[mi], bf[np][0], bf[np][1]);
                    mma_f16(acc[mi][np * 2 + 1], af[mi], bf[np][2], bf[np][3]);
                }
            }
        }
        __syncthreads();
    }

    // ---------------- epilogue ----------------
#pragma unroll
    for (int mi = 0; mi < 4; ++mi) {
#pragma unroll
        for (int half = 0; half < 2; ++half) {
            int li = wm + mi * 16 + grp + half * 8;
            int pp = rowP[li];
            if (pp < 0) continue;
            if (MODE == 0) {
                __half* hrow = g_hh + (size_t)pp * FD + n0;
#pragma unroll
                for (int ni = 0; ni < 8; ++ni) {
                    int nc = wn + ni * 8 + 2 * quad;
                    float v0 = acc[mi][ni][half * 2 + 0] + bias_s[nc];
                    float v1 = acc[mi][ni][half * 2 + 1] + bias_s[nc + 1];
                    v0 = v0 / (1.f + __expf(-v0));        // silu
                    v1 = v1 / (1.f + __expf(-v1));
                    *reinterpret_cast<__half2*>(&hrow[nc]) = __floats2half2_rn(v0, v1);
                }
            } else {
                float wgt = g_pairw[pp];
                float* orow = out + (size_t)(pp >> 1) * HD + n0;
#pragma unroll
                for (int ni = 0; ni < 8; ++ni) {
                    int nc = wn + ni * 8 + 2 * quad;
                    float v0 = acc[mi][ni][half * 2 + 0] + bias_s[nc];
                    float v1 = acc[mi][ni][half * 2 + 1] + bias_s[nc + 1];
                    atomicAdd(&orow[nc], wgt * v0);       // exactly 2 adds/elem:
                    atomicAdd(&orow[nc + 1], wgt * v1);   // commutative => determ.
                }
            }
        }
    }
}

// ---------------- launch -----------------------------------------------------
extern "C" void kernel_launch(void* const* d_in, const int* in_sizes, int n_in,
                              void* d_out, int out_size) {
    const float* x  = (const float*)d_in[0];   // [4,2048,1024]
    const float* gw = (const float*)d_in[1];   // [8,1024]
    const float* w1 = (const float*)d_in[2];   // [8,1024,4096]
    const float* b1 = (const float*)d_in[3];   // [8,4096]
    const float* w2 = (const float*)d_in[4];   // [8,4096,1024]
    const float* b2 = (const float*)d_in[5];   // [8,1024]
    float* out = (float*)d_out;                // [4,2048,1024] fp32

    const int DSM = STAGE_B * STAGES;          // 81408 bytes
    cudaFuncSetAttribute(moe_gemm<0>, cudaFuncAttributeMaxDynamicSharedMemorySize, DSM);
    cudaFuncSetAttribute(moe_gemm<1>, cudaFuncAttributeMaxDynamicSharedMemorySize, DSM);

    int n4 = out_size / 4;
    reset_kernel<<<(n4 + 255) / 256, 256>>>((float4*)out, n4);
    gate_kernel<<<NTOK, 256>>>(x, gw);

    const int wN4 = NE * HD * FD / 4;
    cvt_f2h<<<(wN4 + 255) / 256, 256>>>((const float4*)w1, 0, wN4);
    cvt_f2h<<<(wN4 + 255) / 256, 256>>>((const float4*)w2, 1, wN4);
    const int xN4 = NTOK * HD / 4;
    cvt_f2h<<<(xN4 + 255) / 256, 256>>>((const float4*)x, 2, xN4);

    moe_gemm<0><<<dim3(FD / BN, NTOK / BM, NE), 256, DSM>>>(b1, b2, out);
    moe_gemm<1><<<dim3(HD / BN, NTOK / BM, NE), 256, DSM>>>(b1, b2, out);
}

// round 7
// speedup vs baseline: 1.2575x; 1.2575x over previous
#include <cuda_runtime.h>
#include <cuda_fp16.h>
#include <cstdint>
#include <math.h>

// Problem dims (fixed by the dataset)
#define NTOK   8192            // B*S = 4*2048
#define HD     1024
#define FD     4096
#define NE     8
#define NPAIR  (NTOK * 2)      // top-2

// ---------------- scratch (__device__ globals: allocation-rule safe) --------
__device__ int    g_count[NE];
__device__ int    g_list[NE][NTOK];           // pair ids (t*2+k) per expert
__device__ float  g_pairw[NPAIR];             // gate prob per pair slot
__device__ __half g_w1h[(size_t)NE * HD * FD];   // 67 MB  [e][H][F]
__device__ __half g_w2h[(size_t)NE * FD * HD];   // 67 MB  [e][F][H]
__device__ __half g_xh[(size_t)NTOK * HD];       // 16 MB
__device__ __half g_hh[(size_t)NPAIR * FD];      // 134 MB fp16 intermediate

// ---------------- fp32 -> fp16 convert --------------------------------------
__global__ void cvt_f2h(const float4* __restrict__ s, int which, int n4) {
    int i = blockIdx.x * blockDim.x + threadIdx.x;
    if (i >= n4) return;
    __half2* dst = (which == 0) ? (__half2*)g_w1h
                 : (which == 1) ? (__half2*)g_w2h
                                : (__half2*)g_xh;
    float4 v = s[i];
    uint2 o;
    *reinterpret_cast<__half2*>(&o.x) = __floats2half2_rn(v.x, v.y);
    *reinterpret_cast<__half2*>(&o.y) = __floats2half2_rn(v.z, v.w);
    reinterpret_cast<uint2*>(dst)[i] = o;
}

// ---------------- reset: zero output + counters (every replay!) -------------
__global__ void reset_kernel(float4* out4, int n4) {
    int i = blockIdx.x * blockDim.x + threadIdx.x;
    if (i < n4) out4[i] = make_float4(0.f, 0.f, 0.f, 0.f);
    if (i < NE) g_count[i] = 0;
}

// ---------------- gating: logits, softmax, top-2, build gather lists --------
__global__ void gate_kernel(const float* __restrict__ x,
                            const float* __restrict__ gw) {
    const int t = blockIdx.x;
    const int warp = threadIdx.x >> 5, lane = threadIdx.x & 31;
    __shared__ float logits[NE];
    const float* xr = x + (size_t)t * HD;
    const float* wr = gw + warp * HD;       // 8 warps = 8 experts
    float s = 0.f;
#pragma unroll 8
    for (int h = lane; h < HD; h += 32) s = fmaf(xr[h], wr[h], s);
#pragma unroll
    for (int o = 16; o > 0; o >>= 1) s += __shfl_xor_sync(0xffffffffu, s, o);
    if (lane == 0) logits[warp] = s;
    __syncthreads();
    if (threadIdx.x == 0) {
        float mx = logits[0];
        for (int e = 1; e < NE; e++) mx = fmaxf(mx, logits[e]);
        float pe[NE]; float den = 0.f;
        for (int e = 0; e < NE; e++) { pe[e] = expf(logits[e] - mx); den += pe[e]; }
        int i1 = 0;
        for (int e = 1; e < NE; e++) if (pe[e] > pe[i1]) i1 = e;  // lowest idx on tie
        int i2 = (i1 == 0) ? 1 : 0;
        for (int e = 0; e < NE; e++) if (e != i1 && pe[e] > pe[i2]) i2 = e;
        float inv = 1.f / den;
        int p0 = t * 2, p1 = t * 2 + 1;
        g_pairw[p0] = pe[i1] * inv;
        g_pairw[p1] = pe[i2] * inv;
        int k0 = atomicAdd(&g_count[i1], 1); g_list[i1][k0] = p0;
        int k1 = atomicAdd(&g_count[i2], 1); g_list[i2][k1] = p1;
    }
}

// ---------------- mma / ldmatrix helpers ------------------------------------
__device__ __forceinline__ void mma_f16(float c[4], const uint32_t a[4],
                                        uint32_t b0, uint32_t b1) {
    asm volatile(
        "mma.sync.aligned.m16n8k16.row.col.f32.f16.f16.f32 "
        "{%0,%1,%2,%3},{%4,%5,%6,%7},{%8,%9},{%0,%1,%2,%3};\n"
        : "+f"(c[0]), "+f"(c[1]), "+f"(c[2]), "+f"(c[3])
        : "r"(a[0]), "r"(a[1]), "r"(a[2]), "r"(a[3]), "r"(b0), "r"(b1));
}
__device__ __forceinline__ void ldsm_x4(uint32_t r[4], uint32_t a) {
    asm volatile("ldmatrix.sync.aligned.m8n8.x4.shared.b16 {%0,%1,%2,%3},[%4];\n"
                 : "=r"(r[0]), "=r"(r[1]), "=r"(r[2]), "=r"(r[3]) : "r"(a));
}
__device__ __forceinline__ void ldsm_x4_t(uint32_t r[4], uint32_t a) {
    asm volatile("ldmatrix.sync.aligned.m8n8.x4.trans.shared.b16 {%0,%1,%2,%3},[%4];\n"
                 : "=r"(r[0]), "=r"(r[1]), "=r"(r[2]), "=r"(r[3]) : "r"(a));
}
__device__ __forceinline__ void cp16(uint32_t dst, const void* src) {
    asm volatile("cp.async.cg.shared.global [%0], [%1], 16;\n" :: "r"(dst), "l"(src));
}

// ---------------- grouped gather-GEMM (fp16 in, fp32 acc) -------------------
// CTA tile 128x128, 8 warps of 64x32 (low regs -> 2 CTAs/SM), BK=64, 2 stages.
// MODE 0: g_hh[p] = silu(xh[t] @ w1h[e] + b1[e])        M=cnt K=HD  N=FD
// MODE 1: out[t] += pairw[p]*(g_hh[p] @ w2h[e] + b2[e]) M=cnt K=FD  N=HD
#define BM 128
#define BN 128
#define BK 64
#define AS 72                  // A row stride in halves (144B, 16B-aligned)
#define BS2 136                // B row stride in halves (272B, 16B-aligned)
#define A_BYTES (BM * AS * 2)              // 18432
#define STAGE_B (A_BYTES + BK * BS2 * 2)   // 18432 + 17408 = 35840

template <int MODE>
__global__ __launch_bounds__(256, 2)
void moe_gemm(const float* __restrict__ b1g, const float* __restrict__ b2g,
              float* __restrict__ out) {
    constexpr int K = (MODE == 0) ? HD : FD;
    constexpr int N = (MODE == 0) ? FD : HD;
    constexpr int KT = K / BK;
    const int e = blockIdx.z;
    const int cnt = g_count[e];
    const int rowBase = blockIdx.y * BM;
    if (rowBase >= cnt) return;                 // idle worst-case block
    const int n0 = blockIdx.x * BN;
    const __half* __restrict__ Bmat =
        (MODE == 0) ? (g_w1h + (size_t)e * HD * FD) : (g_w2h + (size_t)e * FD * HD);
    const float* __restrict__ bias = (MODE == 0) ? (b1g + e * FD) : (b2g + e * HD);

    extern __shared__ __align__(128) char dsm[];
    __shared__ int rowP[BM];
    __shared__ const __half* rowSrc[BM];
    __shared__ float bias_s[BN];

    const int tid = threadIdx.x;
    if (tid < BM) {
        int gi = rowBase + tid;
        int pp = (gi < cnt) ? g_list[e][gi] : -1;
        rowP[tid] = pp;
        rowSrc[tid] = (MODE == 0)
            ? ((pp >= 0) ? g_xh + (size_t)(pp >> 1) * HD : g_xh)
            : ((pp >= 0) ? g_hh + (size_t)pp * FD : g_hh);
        bias_s[tid] = bias[n0 + tid];          // BN==128
    }
    __syncthreads();

    const int lane = tid & 31, warp = tid >> 5;
    const int wm = (warp & 1) * 64;            // 2x4 warp grid, 64x32 warp tile
    const int wn = (warp >> 1) * 32;
    const int grp = lane >> 2, quad = lane & 3;
    const uint32_t dsm32 = (uint32_t)__cvta_generic_to_shared(dsm);

    float acc[4][4][4];
#pragma unroll
    for (int a = 0; a < 4; a++)
#pragma unroll
        for (int b = 0; b < 4; b++)
#pragma unroll
            for (int c = 0; c < 4; c++) acc[a][b][c] = 0.f;

    auto fill = [&](int s, int kt) {
        const int k0 = kt * BK;
        const uint32_t aB = dsm32 + s * STAGE_B;
        const uint32_t bB = aB + A_BYTES;
#pragma unroll
        for (int i = 0; i < 4; ++i) {           // A: 128 rows x 8 chunks = 1024
            int id = tid + i * 256;
            int r = id >> 3, ch = id & 7;
            cp16(aB + (r * AS + ch * 8) * 2, rowSrc[r] + k0 + ch * 8);
        }
#pragma unroll
        for (int i = 0; i < 4; ++i) {           // B: 64 rows x 16 chunks = 1024
            int id = tid + i * 256;
            int r = id >> 4, ch = id & 15;
            cp16(bB + (r * BS2 + ch * 8) * 2,
                 Bmat + (size_t)(k0 + r) * N + n0 + ch * 8);
        }
        asm volatile("cp.async.commit_group;\n" ::: "memory");
    };

    fill(0, 0);
    fill(1, 1);
    for (int kt = 0; kt < KT; ++kt) {
        if (kt + 1 < KT) asm volatile("cp.async.wait_group 1;\n" ::: "memory");
        else             asm volatile("cp.async.wait_group 0;\n" ::: "memory");
        __syncthreads();
        const int s = kt & 1;
        const uint32_t aB = dsm32 + s * STAGE_B;
        const uint32_t bB = aB + A_BYTES;
#pragma unroll
        for (int ks = 0; ks < 4; ++ks) {        // four k16 steps per BK=64
            uint32_t af[4][4];
#pragma unroll
            for (int mi = 0; mi < 4; ++mi) {
                int row = wm + mi * 16 + (lane & 15);
                int col = ks * 16 + (lane >> 4) * 8;
                ldsm_x4(af[mi], aB + (row * AS + col) * 2);
            }
            uint32_t bf[2][4];
#pragma unroll
            for (int np = 0; np < 2; ++np) {
                int m = lane >> 3;
                int kk = ks * 16 + (m & 1) * 8 + (lane & 7);
                int nn = wn + np * 16 + (m >> 1) * 8;
                ldsm_x4_t(bf[np], bB + (kk * BS2 + nn) * 2);
            }
#pragma unroll
            for (int mi = 0; mi < 4; ++mi) {
#pragma unroll
                for (int np = 0; np < 2; ++np) {
                    mma_f16(acc[mi][np * 2 + 0], af[mi], bf[np][0], bf[np][1]);
                    mma_f16(acc[mi][np * 2 + 1], af[mi], bf[np][2], bf[np][3]);
                }
            }
        }
        __syncthreads();
        if (kt + 2 < KT) fill(s, kt + 2);       // stage s free after this compute
    }

    // ---------------- epilogue ----------------
#pragma unroll
    for (int mi = 0; mi < 4; ++mi) {
#pragma unroll
        for (int half = 0; half < 2; ++half) {
            int li = wm + mi * 16 + grp + half * 8;
            int pp = rowP[li];
            if (pp < 0) continue;
            if (MODE == 0) {
                __half* hrow = g_hh + (size_t)pp * FD + n0;
#pragma unroll
                for (int ni = 0; ni < 4; ++ni) {
                    int nc = wn + ni * 8 + 2 * quad;
                    float v0 = acc[mi][ni][half * 2 + 0] + bias_s[nc];
                    float v1 = acc[mi][ni][half * 2 + 1] + bias_s[nc + 1];
                    v0 = v0 / (1.f + __expf(-v0));        // silu
                    v1 = v1 / (1.f + __expf(-v1));
                    *reinterpret_cast<__half2*>(&hrow[nc]) = __floats2half2_rn(v0, v1);
                }
            } else {
                float wgt = g_pairw[pp];
                float* orow = out + (size_t)(pp >> 1) * HD + n0;
#pragma unroll
                for (int ni = 0; ni < 4; ++ni) {
                    int nc = wn + ni * 8 + 2 * quad;
                    float v0 = acc[mi][ni][half * 2 + 0] + bias_s[nc];
                    float v1 = acc[mi][ni][half * 2 + 1] + bias_s[nc + 1];
                    atomicAdd(&orow[nc], wgt * v0);       // exactly 2 adds/elem:
                    atomicAdd(&orow[nc + 1], wgt * v1);   // commutative => determ.
                }
            }
        }
    }
}

// ---------------- launch -----------------------------------------------------
extern "C" void kernel_launch(void* const* d_in, const int* in_sizes, int n_in,
                              void* d_out, int out_size) {
    const float* x  = (const float*)d_in[0];   // [4,2048,1024]
    const float* gw = (const float*)d_in[1];   // [8,1024]
    const float* w1 = (const float*)d_in[2];   // [8,1024,4096]
    const float* b1 = (const float*)d_in[3];   // [8,4096]
    const float* w2 = (const float*)d_in[4];   // [8,4096,1024]
    const float* b2 = (const float*)d_in[5];   // [8,1024]
    float* out = (float*)d_out;                // [4,2048,1024] fp32

    const int DSM = STAGE_B * 2;               // 71680 bytes
    cudaFuncSetAttribute(moe_gemm<0>, cudaFuncAttributeMaxDynamicSharedMemorySize, DSM);
    cudaFuncSetAttribute(moe_gemm<1>, cudaFuncAttributeMaxDynamicSharedMemorySize, DSM);

    int n4 = out_size / 4;
    reset_kernel<<<(n4 + 255) / 256, 256>>>((float4*)out, n4);
    gate_kernel<<<NTOK, 256>>>(x, gw);

    const int wN4 = NE * HD * FD / 4;
    cvt_f2h<<<(wN4 + 255) / 256, 256>>>((const float4*)w1, 0, wN4);
    cvt_f2h<<<(wN4 + 255) / 256, 256>>>((const float4*)w2, 1, wN4);
    const int xN4 = NTOK * HD / 4;
    cvt_f2h<<<(xN4 + 255) / 256, 256>>>((const float4*)x, 2, xN4);

    moe_gemm<0><<<dim3(FD / BN, NTOK / BM, NE), 256, DSM>>>(b1, b2, out);
    moe_gemm<1><<<dim3(HD / BN, NTOK / BM, NE), 256, DSM>>>(b1, b2, out);
}

// round 8
// speedup vs baseline: 1.3001x; 1.0339x over previous
#include <cuda_runtime.h>
#include <cuda_fp16.h>
#include <cstdint>
#include <math.h>

// Problem dims (fixed by the dataset)
#define NTOK   8192            // B*S = 4*2048
#define HD     1024
#define FD     4096
#define NE     8
#define NPAIR  (NTOK * 2)      // top-2

// ---------------- scratch (__device__ globals: allocation-rule safe) --------
__device__ int    g_count[NE];
__device__ int    g_list[NE][NTOK];           // pair ids (t*2+k) per expert
__device__ float  g_pairw[NPAIR];             // gate prob per pair slot
__device__ __half g_w1h[(size_t)NE * HD * FD];   // 67 MB  [e][H][F]
__device__ __half g_w2h[(size_t)NE * FD * HD];   // 67 MB  [e][F][H]
__device__ __half g_xh[(size_t)NTOK * HD];       // 16 MB
__device__ __half g_hh[(size_t)NPAIR * FD];      // 134 MB fp16 intermediate

// ---------------- fp32 -> fp16 convert --------------------------------------
__global__ void cvt_f2h(const float4* __restrict__ s, int which, int n4) {
    int i = blockIdx.x * blockDim.x + threadIdx.x;
    if (i >= n4) return;
    __half2* dst = (which == 0) ? (__half2*)g_w1h
                 : (which == 1) ? (__half2*)g_w2h
                                : (__half2*)g_xh;
    float4 v = s[i];
    uint2 o;
    *reinterpret_cast<__half2*>(&o.x) = __floats2half2_rn(v.x, v.y);
    *reinterpret_cast<__half2*>(&o.y) = __floats2half2_rn(v.z, v.w);
    reinterpret_cast<uint2*>(dst)[i] = o;
}

// ---------------- reset: zero output + counters (every replay!) -------------
__global__ void reset_kernel(float4* out4, int n4) {
    int i = blockIdx.x * blockDim.x + threadIdx.x;
    if (i < n4) out4[i] = make_float4(0.f, 0.f, 0.f, 0.f);
    if (i < NE) g_count[i] = 0;
}

// ---------------- gating: logits, softmax, top-2, build gather lists --------
__global__ void gate_kernel(const float* __restrict__ x,
                            const float* __restrict__ gw) {
    const int t = blockIdx.x;
    const int warp = threadIdx.x >> 5, lane = threadIdx.x & 31;
    __shared__ float logits[NE];
    const float* xr = x + (size_t)t * HD;
    const float* wr = gw + warp * HD;       // 8 warps = 8 experts
    float s = 0.f;
#pragma unroll 8
    for (int h = lane; h < HD; h += 32) s = fmaf(xr[h], wr[h], s);
#pragma unroll
    for (int o = 16; o > 0; o >>= 1) s += __shfl_xor_sync(0xffffffffu, s, o);
    if (lane == 0) logits[warp] = s;
    __syncthreads();
    if (threadIdx.x == 0) {
        float mx = logits[0];
        for (int e = 1; e < NE; e++) mx = fmaxf(mx, logits[e]);
        float pe[NE]; float den = 0.f;
        for (int e = 0; e < NE; e++) { pe[e] = expf(logits[e] - mx); den += pe[e]; }
        int i1 = 0;
        for (int e = 1; e < NE; e++) if (pe[e] > pe[i1]) i1 = e;  // lowest idx on tie
        int i2 = (i1 == 0) ? 1 : 0;
        for (int e = 0; e < NE; e++) if (e != i1 && pe[e] > pe[i2]) i2 = e;
        float inv = 1.f / den;
        int p0 = t * 2, p1 = t * 2 + 1;
        g_pairw[p0] = pe[i1] * inv;
        g_pairw[p1] = pe[i2] * inv;
        int k0 = atomicAdd(&g_count[i1], 1); g_list[i1][k0] = p0;
        int k1 = atomicAdd(&g_count[i2], 1); g_list[i2][k1] = p1;
    }
}

// ---------------- mma / ldmatrix helpers ------------------------------------
__device__ __forceinline__ void mma_f16(float c[4], const uint32_t a[4],
                                        uint32_t b0, uint32_t b1) {
    asm volatile(
        "mma.sync.aligned.m16n8k16.row.col.f32.f16.f16.f32 "
        "{%0,%1,%2,%3},{%4,%5,%6,%7},{%8,%9},{%0,%1,%2,%3};\n"
        : "+f"(c[0]), "+f"(c[1]), "+f"(c[2]), "+f"(c[3])
        : "r"(a[0]), "r"(a[1]), "r"(a[2]), "r"(a[3]), "r"(b0), "r"(b1));
}
__device__ __forceinline__ void ldsm_x4(uint32_t r[4], uint32_t a) {
    asm volatile("ldmatrix.sync.aligned.m8n8.x4.shared.b16 {%0,%1,%2,%3},[%4];\n"
                 : "=r"(r[0]), "=r"(r[1]), "=r"(r[2]), "=r"(r[3]) : "r"(a));
}
__device__ __forceinline__ void ldsm_x4_t(uint32_t r[4], uint32_t a) {
    asm volatile("ldmatrix.sync.aligned.m8n8.x4.trans.shared.b16 {%0,%1,%2,%3},[%4];\n"
                 : "=r"(r[0]), "=r"(r[1]), "=r"(r[2]), "=r"(r[3]) : "r"(a));
}
__device__ __forceinline__ void cp16(uint32_t dst, const void* src) {
    asm volatile("cp.async.cg.shared.global [%0], [%1], 16;\n" :: "r"(dst), "l"(src));
}
__device__ __forceinline__ void redv4(float* a, float v0, float v1, float v2, float v3) {
    asm volatile("red.global.add.v4.f32 [%0], {%1,%2,%3,%4};"
                 :: "l"(a), "f"(v0), "f"(v1), "f"(v2), "f"(v3) : "memory");
}

// ---------------- grouped gather-GEMM (fp16 in, fp32 acc) -------------------
// CTA tile 128x128, 8 warps of 64x32 (low regs -> 2 CTAs/SM), BK=64,
// 3-stage cp.async pipeline with ONE barrier per k-iteration.
// MODE 0: g_hh[p] = silu(xh[t] @ w1h[e] + b1[e])        M=cnt K=HD  N=FD
// MODE 1: out[t] += pairw[p]*(g_hh[p] @ w2h[e] + b2[e]) M=cnt K=FD  N=HD
#define BM 128
#define BN 128
#define BK 64
#define STAGES 3
#define AS 72                  // A row stride in halves (144B, 16B-aligned)
#define BS2 136                // B row stride in halves (272B, 16B-aligned)
#define A_BYTES (BM * AS * 2)              // 18432
#define STAGE_B (A_BYTES + BK * BS2 * 2)   // 18432 + 17408 = 35840

template <int MODE>
__global__ __launch_bounds__(256, 2)
void moe_gemm(const float* __restrict__ b1g, const float* __restrict__ b2g,
              float* __restrict__ out) {
    constexpr int K = (MODE == 0) ? HD : FD;
    constexpr int N = (MODE == 0) ? FD : HD;
    constexpr int KT = K / BK;
    const int e = blockIdx.z;
    const int cnt = g_count[e];
    const int rowBase = blockIdx.y * BM;
    if (rowBase >= cnt) return;                 // idle worst-case block
    const int n0 = blockIdx.x * BN;
    const __half* __restrict__ Bmat =
        (MODE == 0) ? (g_w1h + (size_t)e * HD * FD) : (g_w2h + (size_t)e * FD * HD);
    const float* __restrict__ bias = (MODE == 0) ? (b1g + e * FD) : (b2g + e * HD);

    extern __shared__ __align__(128) char dsm[];
    __shared__ int rowP[BM];
    __shared__ const __half* rowSrc[BM];
    __shared__ float bias_s[BN];

    const int tid = threadIdx.x;
    if (tid < BM) {
        int gi = rowBase + tid;
        int pp = (gi < cnt) ? g_list[e][gi] : -1;
        rowP[tid] = pp;
        rowSrc[tid] = (MODE == 0)
            ? ((pp >= 0) ? g_xh + (size_t)(pp >> 1) * HD : g_xh)
            : ((pp >= 0) ? g_hh + (size_t)pp * FD : g_hh);
        bias_s[tid] = bias[n0 + tid];          // BN==128
    }
    __syncthreads();

    const int lane = tid & 31, warp = tid >> 5;
    const int wm = (warp & 1) * 64;            // 2x4 warp grid, 64x32 warp tile
    const int wn = (warp >> 1) * 32;
    const int grp = lane >> 2, quad = lane & 3;
    const uint32_t dsm32 = (uint32_t)__cvta_generic_to_shared(dsm);

    float acc[4][4][4];
#pragma unroll
    for (int a = 0; a < 4; a++)
#pragma unroll
        for (int b = 0; b < 4; b++)
#pragma unroll
            for (int c = 0; c < 4; c++) acc[a][b][c] = 0.f;

    auto fill = [&](int s, int kt) {
        const int k0 = kt * BK;
        const uint32_t aB = dsm32 + s * STAGE_B;
        const uint32_t bB = aB + A_BYTES;
#pragma unroll
        for (int i = 0; i < 4; ++i) {           // A: 128 rows x 8 chunks = 1024
            int id = tid + i * 256;
            int r = id >> 3, ch = id & 7;
            cp16(aB + (r * AS + ch * 8) * 2, rowSrc[r] + k0 + ch * 8);
        }
#pragma unroll
        for (int i = 0; i < 4; ++i) {           // B: 64 rows x 16 chunks = 1024
            int id = tid + i * 256;
            int r = id >> 4, ch = id & 15;
            cp16(bB + (r * BS2 + ch * 8) * 2,
                 Bmat + (size_t)(k0 + r) * N + n0 + ch * 8);
        }
        asm volatile("cp.async.commit_group;\n" ::: "memory");
    };

    fill(0, 0);
    fill(1, 1);
    for (int kt = 0; kt < KT; ++kt) {
        if (kt + 1 < KT) asm volatile("cp.async.wait_group 1;\n" ::: "memory");
        else             asm volatile("cp.async.wait_group 0;\n" ::: "memory");
        __syncthreads();                        // the ONLY barrier per kt
        if (kt + 2 < KT) fill((kt + 2) % STAGES, kt + 2);   // consumed at kt-1
        const int s = kt % STAGES;
        const uint32_t aB = dsm32 + s * STAGE_B;
        const uint32_t bB = aB + A_BYTES;
#pragma unroll
        for (int ks = 0; ks < 4; ++ks) {        // four k16 steps per BK=64
            uint32_t af[4][4];
#pragma unroll
            for (int mi = 0; mi < 4; ++mi) {
                int row = wm + mi * 16 + (lane & 15);
                int col = ks * 16 + (lane >> 4) * 8;
                ldsm_x4(af[mi], aB + (row * AS + col) * 2);
            }
            uint32_t bf[2][4];
#pragma unroll
            for (int np = 0; np < 2; ++np) {
                int m = lane >> 3;
                int kk = ks * 16 + (m & 1) * 8 + (lane & 7);
                int nn = wn + np * 16 + (m >> 1) * 8;
                ldsm_x4_t(bf[np], bB + (kk * BS2 + nn) * 2);
            }
#pragma unroll
            for (int mi = 0; mi < 4; ++mi) {
#pragma unroll
                for (int np = 0; np < 2; ++np) {
                    mma_f16(acc[mi][np * 2 + 0], af[mi], bf[np][0], bf[np][1]);
                    mma_f16(acc[mi][np * 2 + 1], af[mi], bf[np][2], bf[np][3]);
                }
            }
        }
    }
    __syncthreads();                            // stage buffers now reusable

    // ---------------- epilogue (smem-staged, coalesced global ops) ----------
    if (MODE == 0) {
        __half* stg = (__half*)dsm;             // [128][136] halves = 34.8 KB
#pragma unroll
        for (int mi = 0; mi < 4; ++mi)
#pragma unroll
            for (int half = 0; half < 2; ++half) {
                int li = wm + mi * 16 + grp + half * 8;
#pragma unroll
                for (int ni = 0; ni < 4; ++ni) {
                    int nc = wn + ni * 8 + 2 * quad;
                    float v0 = acc[mi][ni][half * 2 + 0] + bias_s[nc];
                    float v1 = acc[mi][ni][half * 2 + 1] + bias_s[nc + 1];
                    v0 = v0 / (1.f + __expf(-v0));        // silu
                    v1 = v1 / (1.f + __expf(-v1));
                    *reinterpret_cast<__half2*>(&stg[li * 136 + nc]) =
                        __floats2half2_rn(v0, v1);
                }
            }
        __syncthreads();
        for (int i = tid; i < BM * 16; i += 256) {   // 16B chunks, coalesced
            int r = i >> 4, ch = i & 15;
            int pp = rowP[r];
            if (pp < 0) continue;
            *reinterpret_cast<uint4*>(g_hh + (size_t)pp * FD + n0 + ch * 8) =
                *reinterpret_cast<uint4*>(&stg[r * 136 + ch * 8]);
        }
    } else {
        float* stg = (float*)dsm;               // [128][132] floats = 67.6 KB
#pragma unroll
        for (int mi = 0; mi < 4; ++mi)
#pragma unroll
            for (int half = 0; half < 2; ++half) {
                int li = wm + mi * 16 + grp + half * 8;
                int pp = rowP[li];
                float wgt = (pp >= 0) ? g_pairw[pp] : 0.f;
#pragma unroll
                for (int ni = 0; ni < 4; ++ni) {
                    int nc = wn + ni * 8 + 2 * quad;
                    stg[li * 132 + nc]     = (acc[mi][ni][half * 2 + 0] + bias_s[nc]) * wgt;
                    stg[li * 132 + nc + 1] = (acc[mi][ni][half * 2 + 1] + bias_s[nc + 1]) * wgt;
                }
            }
        __syncthreads();
        for (int i = tid; i < BM * 32; i += 256) {   // 16B-aligned v4 atomics
            int r = i >> 5, ch = i & 31;
            int pp = rowP[r];
            if (pp < 0) continue;
            float* orow = out + (size_t)(pp >> 1) * HD + n0 + ch * 4;
            const float* v = &stg[r * 132 + ch * 4];
            redv4(orow, v[0], v[1], v[2], v[3]);     // 2 commutative adds/elem
        }
    }
}

// ---------------- launch -----------------------------------------------------
extern "C" void kernel_launch(void* const* d_in, const int* in_sizes, int n_in,
                              void* d_out, int out_size) {
    const float* x  = (const float*)d_in[0];   // [4,2048,1024]
    const float* gw = (const float*)d_in[1];   // [8,1024]
    const float* w1 = (const float*)d_in[2];   // [8,1024,4096]
    const float* b1 = (const float*)d_in[3];   // [8,4096]
    const float* w2 = (const float*)d_in[4];   // [8,4096,1024]
    const float* b2 = (const float*)d_in[5];   // [8,1024]
    float* out = (float*)d_out;                // [4,2048,1024] fp32

    const int DSM = STAGE_B * STAGES;          // 107520 bytes (2 CTAs = 210 KB)
    cudaFuncSetAttribute(moe_gemm<0>, cudaFuncAttributeMaxDynamicSharedMemorySize, DSM);
    cudaFuncSetAttribute(moe_gemm<1>, cudaFuncAttributeMaxDynamicSharedMemorySize, DSM);

    int n4 = out_size / 4;
    reset_kernel<<<(n4 + 255) / 256, 256>>>((float4*)out, n4);
    gate_kernel<<<NTOK, 256>>>(x, gw);

    const int wN4 = NE * HD * FD / 4;
    cvt_f2h<<<(wN4 + 255) / 256, 256>>>((const float4*)w1, 0, wN4);
    cvt_f2h<<<(wN4 + 255) / 256, 256>>>((const float4*)w2, 1, wN4);
    const int xN4 = NTOK * HD / 4;
    cvt_f2h<<<(xN4 + 255) / 256, 256>>>((const float4*)x, 2, xN4);

    moe_gemm<0><<<dim3(FD / BN, NTOK / BM, NE), 256, DSM>>>(b1, b2, out);
    moe_gemm<1><<<dim3(HD / BN, NTOK / BM, NE), 256, DSM>>>(b1, b2, out);
}